// round 1
// baseline (speedup 1.0000x reference)
#include <cuda_runtime.h>

// Problem constants
#define NB    32
#define NMEL  128
#define TT    8192
#define NKEYS 88

// Precomputed (double-precision, replicating numpy _mel_frequencies + argmin):
// key k (MIDI k+21) -> nearest of 128 mel bins (fmax=8000).
__device__ static const int KB[NKEYS] = {
   1,  1,  1,  1,  1,
   2,  2,  2,  2,  2,  2,  2,  2,  2,
   3,  3,  3,  3,  3,  3,
   4,  4,  4,  4,
   5,  5,  5,
   6,  6,  6,
   7,  7,  7,
   8,  8,
   9,  9,
  10, 10,
  11,
  12, 12,
  13,
  14,
  15,
  16,
  17, 17,
  19, 20, 21, 22, 23, 25, 26, 28, 29, 31, 33, 35, 37, 39, 42, 44, 46, 49,
  51, 53, 56, 58, 60, 63, 65, 68, 70, 72, 75, 77, 79, 82, 84, 86, 89, 91,
  93, 96, 98, 101
};

// Row r of mel is needed iff r is a key bin, or 2*bin (bin<64), or 3*bin (bin<43).
// 89 rows total.
__device__ static const bool NEEDED[NMEL] = {
  /*  0- 9 */ 0,1,1,1,1,1,1,1,1,1,
  /* 10-19 */ 1,1,1,1,1,1,1,1,1,1,
  /* 20-29 */ 1,1,1,1,1,1,1,1,1,1,
  /* 30-39 */ 1,1,1,1,1,1,1,1,1,1,
  /* 40-49 */ 1,0,1,0,1,1,1,0,1,1,
  /* 50-59 */ 1,1,1,1,0,0,1,1,1,0,
  /* 60-69 */ 1,0,1,1,0,1,1,0,1,1,
  /* 70-79 */ 1,0,1,0,1,1,0,1,1,1,
  /* 80-89 */ 0,0,1,0,1,0,1,1,1,1,
  /* 90-99 */ 0,1,1,1,0,0,1,0,1,1,
  /*100-109*/ 0,1,1,0,0,1,1,0,0,0,
  /*110-119*/ 0,1,1,0,0,0,1,1,0,0,
  /*120-127*/ 1,0,0,0,0,0,1,0
};

__global__ void __launch_bounds__(128)
hps_key_probs_kernel(const float* __restrict__ mel,
                     float* __restrict__ out,
                     int write_two)
{
    const int p = blockIdx.x * 128 + threadIdx.x;   // 0..262143
    const int b = p >> 13;                           // /8192
    const int t = p & (TT - 1);

    const float* __restrict__ mb = mel + (size_t)b * (NMEL * TT) + t;

    // exp of every needed mel row (static indices -> registers)
    float e[NMEL];
    #pragma unroll
    for (int r = 0; r < NMEL; ++r) {
        if (NEEDED[r]) e[r] = expf(mb[(size_t)r * TT]);
    }

    // v_k = hps value at key bin k (matches reference product association:
    // ((exp(m)*exp(2m))*exp(3m)) with conditional factors)
    auto vk = [&](int k) -> float {
        const int bn = KB[k];
        float x = e[bn];
        if (bn < 64) x = x * e[2 * bn];
        if (bn < 43) x = x * e[3 * bn];
        return x;
    };

    const float NEG = __int_as_float(0xff800000);   // -inf padding

    // Streaming top-16 selection: 6 groups of 16 (last padded with -inf).
    // Each group: bitonic sort descending, then merge-keep-top-16 with running tt[].
    float tt[16];
    float g[16];

    #pragma unroll
    for (int grp = 0; grp < 6; ++grp) {
        #pragma unroll
        for (int u = 0; u < 16; ++u) {
            const int k = grp * 16 + u;
            g[u] = (k < NKEYS) ? vk(k) : NEG;
        }
        // bitonic sort g[16] descending (all indices compile-time after unroll)
        #pragma unroll
        for (int kk = 2; kk <= 16; kk <<= 1) {
            #pragma unroll
            for (int j = kk >> 1; j > 0; j >>= 1) {
                #pragma unroll
                for (int i = 0; i < 16; ++i) {
                    const int l = i ^ j;
                    if (l > i) {
                        const float a = g[i], c = g[l];
                        if ((i & kk) == 0) { g[i] = fmaxf(a, c); g[l] = fminf(a, c); }
                        else               { g[i] = fminf(a, c); g[l] = fmaxf(a, c); }
                    }
                }
            }
        }
        if (grp == 0) {
            #pragma unroll
            for (int i = 0; i < 16; ++i) tt[i] = g[i];
        } else {
            // top-16 of (tt desc, g desc): elementwise max against reversed g
            // gives the top-16 multiset as a bitonic sequence, then clean it.
            #pragma unroll
            for (int i = 0; i < 16; ++i) tt[i] = fmaxf(tt[i], g[15 - i]);
            #pragma unroll
            for (int j = 8; j > 0; j >>= 1) {
                #pragma unroll
                for (int i = 0; i < 16; ++i) {
                    const int l = i ^ j;
                    if (l > i) {
                        const float a = tt[i], c = tt[l];
                        tt[i] = fmaxf(a, c); tt[l] = fminf(a, c);
                    }
                }
            }
        }
    }

    // quantile(0.85) over 88: interpolate ascending-sorted[73] (=15th largest)
    // and sorted[74] (=14th largest), exactly like jnp.quantile 'linear'.
    const float s74  = tt[13];               // 14th largest
    const float s73  = tt[14];               // 15th largest
    const float idx  = 0.85f * 87.0f;
    const float frac = idx - 73.0f;
    const float thresh = s73 * (1.0f - frac) + s74 * frac;

    float* o0 = out + (size_t)b * (NKEYS * TT) + t;
    const size_t half = (size_t)NB * NKEYS * TT;
    #pragma unroll
    for (int k = 0; k < NKEYS; ++k) {
        const float pv = (vk(k) >= thresh) ? 1.0f : 0.0f;
        o0[(size_t)k * TT] = pv;
        if (write_two) o0[(size_t)k * TT + half] = pv;
    }
}

extern "C" void kernel_launch(void* const* d_in, const int* in_sizes, int n_in,
                              void* d_out, int out_size)
{
    const float* mel = (const float*)d_in[0];
    float* out = (float*)d_out;
    // output is the tuple (probs, probs): two concatenated copies if room
    const long long half = (long long)NB * NKEYS * TT;   // 23,068,672
    const int write_two = (out_size >= 2 * half) ? 1 : 0;

    const int points = NB * TT;          // 262144
    hps_key_probs_kernel<<<points / 128, 128>>>(mel, out, write_two);
}